// round 6
// baseline (speedup 1.0000x reference)
#include <cuda_runtime.h>
#include <cuda_bf16.h>
#include <cstdint>
#include <math.h>

#define BATCH 4
#define SEQ   4096
#define CDIM  1024
#define HEADS 16
#define HDIM  64
#define MROWS 16384
#define K2    2048          // stored split K: [hi | lo]
#define NKIT  48            // virtual K blocks of 64 (3 segments x 16)
#define BH    64

// ---------------- scratch ----------------
__device__ __nv_bfloat16 g_A[(size_t)MROWS * K2];   // [hi|lo]
__device__ __nv_bfloat16 g_Bq[(size_t)3072 * K2];   // W_qkv split, K-major
__device__ __nv_bfloat16 g_Bp[(size_t)CDIM * K2];   // W_proj split
__device__ float g_q[(size_t)MROWS * CDIM];
__device__ float g_k[(size_t)MROWS * CDIM];
__device__ float g_v[(size_t)MROWS * CDIM];
__device__ float g_ctx[BH * HDIM * HDIM];
__device__ float g_colsum[BH * HDIM];

__device__ __forceinline__ uint32_t smem_u32(const void* p) {
    uint32_t a;
    asm("{ .reg .u64 t; cvta.to.shared.u64 t, %1; cvt.u32.u64 %0, t; }" : "=r"(a) : "l"(p));
    return a;
}
__device__ __forceinline__ void cpa16(uint32_t saddr, const void* g) {
    asm volatile("cp.async.cg.shared.global [%0], [%1], 16;" :: "r"(saddr), "l"(g));
}
#define CPA_COMMIT() asm volatile("cp.async.commit_group;" ::: "memory")

__device__ __forceinline__ void ldm_x4(uint32_t* f, uint32_t addr) {
    asm volatile("ldmatrix.sync.aligned.m8n8.x4.shared.b16 {%0,%1,%2,%3}, [%4];"
        : "=r"(f[0]), "=r"(f[1]), "=r"(f[2]), "=r"(f[3]) : "r"(addr));
}
__device__ __forceinline__ void mma_bf16(float* d, const uint32_t* a, uint32_t b0, uint32_t b1) {
    asm volatile("mma.sync.aligned.m16n8k16.row.col.f32.bf16.bf16.f32 "
        "{%0,%1,%2,%3}, {%4,%5,%6,%7}, {%8,%9}, {%0,%1,%2,%3};"
        : "+f"(d[0]), "+f"(d[1]), "+f"(d[2]), "+f"(d[3])
        : "r"(a[0]), "r"(a[1]), "r"(a[2]), "r"(a[3]), "r"(b0), "r"(b1));
}

// ---------------- HMMA GEMM ----------------
// Virtual K = 3072 : 48 blocks of 64. seg0 Ahi*Bhi (vi<16), seg1 Ahi*Blo, seg2 Alo*Bhi.
// CTA tile 128x256, BK=64, 256 thr (8 warps, 2x4), warp tile 64x64.
// 3-stage cp.async, 1 sync/iter. 1 CTA/SM.
#define SROW   72               // smem row stride elems (144B) — ldmatrix conflict-free
#define ABYTES (128 * SROW * 2)   // 18432
#define BBYTES (256 * SROW * 2)   // 36864
#define STGB   (ABYTES + BBYTES)  // 55296
#define GSMEM  (3 * STGB)         // 165888

__device__ __forceinline__ void load_stage(uint32_t dst,
        const __nv_bfloat16* __restrict__ A, const __nv_bfloat16* __restrict__ B,
        int vi, int bm, int bn, int tid) {
    int ka, kb;
    if (vi < 16)      { ka = vi;      kb = vi; }        // hi * hi
    else if (vi < 32) { ka = vi - 16; kb = vi; }        // hi * lo
    else              { ka = vi - 16; kb = vi - 32; }   // lo * hi
#pragma unroll
    for (int l = 0; l < 4; l++) {                       // A: 128 rows x 8 chunks
        int c = tid + l * 256;
        int row = c >> 3, pos = c & 7;
        uint32_t so = (uint32_t)(row * SROW + pos * 8) * 2;
        cpa16(dst + so, A + (size_t)(bm + row) * K2 + ka * 64 + pos * 8);
    }
#pragma unroll
    for (int l = 0; l < 8; l++) {                       // B: 256 rows x 8 chunks
        int c = tid + l * 256;
        int row = c >> 3, pos = c & 7;
        uint32_t so = (uint32_t)(row * SROW + pos * 8) * 2;
        cpa16(dst + ABYTES + so, B + (size_t)(bn + row) * K2 + kb * 64 + pos * 8);
    }
    CPA_COMMIT();
}

template<int MODE>
__global__ void __launch_bounds__(256, 1)
gemm_hmma(const __nv_bfloat16* __restrict__ A, const __nv_bfloat16* __restrict__ Bm,
          const float* __restrict__ bias, float* __restrict__ Cout, int Nn)
{
    extern __shared__ __nv_bfloat16 dsm[];
    const uint32_t s0 = smem_u32(dsm);

    const int tid = threadIdx.x, wid = tid >> 5, lane = tid & 31;
    const int bm = blockIdx.y * 128, bn = blockIdx.x * 256;
    const int mbase = (wid & 1) * 64, nbase = (wid >> 1) * 64;

    float acc[4][8][4];
#pragma unroll
    for (int i = 0; i < 4; i++)
#pragma unroll
        for (int j = 0; j < 8; j++)
#pragma unroll
            for (int r = 0; r < 4; r++) acc[i][j][r] = 0.f;

    const int a_row = lane & 15, a_kof = (lane >> 4) * 8;
    const int b_row = (lane & 7) + ((lane >> 4) & 1) * 8;
    const int b_kof = ((lane >> 3) & 1) * 8;

    load_stage(s0,        A, Bm, 0, bm, bn, tid);
    load_stage(s0 + STGB, A, Bm, 1, bm, bn, tid);

    for (int i = 0; i < NKIT; i++) {
        if (i + 2 < NKIT) asm volatile("cp.async.wait_group 1;" ::: "memory");
        else              asm volatile("cp.async.wait_group 0;" ::: "memory");
        __syncthreads();
        if (i + 2 < NKIT)
            load_stage(s0 + ((i + 2) % 3) * STGB, A, Bm, i + 2, bm, bn, tid);

        const uint32_t sa  = s0 + (i % 3) * STGB;
        const uint32_t sbB = sa + ABYTES;
#pragma unroll
        for (int kc = 0; kc < 4; kc++) {
            uint32_t af[4][4], bfm[4][4];
#pragma unroll
            for (int mt = 0; mt < 4; mt++)
                ldm_x4(af[mt], sa + (uint32_t)((mbase + mt * 16 + a_row) * SROW
                                               + kc * 16 + a_kof) * 2);
#pragma unroll
            for (int np = 0; np < 4; np++)
                ldm_x4(bfm[np], sbB + (uint32_t)((nbase + np * 16 + b_row) * SROW
                                                 + kc * 16 + b_kof) * 2);
#pragma unroll
            for (int mt = 0; mt < 4; mt++)
#pragma unroll
                for (int nt = 0; nt < 8; nt++)
                    mma_bf16(acc[mt][nt], af[mt],
                             bfm[nt >> 1][(nt & 1) * 2], bfm[nt >> 1][(nt & 1) * 2 + 1]);
        }
    }

    // epilogue
    const int r0 = lane >> 2, cpair = (lane & 3) * 2;
#pragma unroll
    for (int mt = 0; mt < 4; mt++) {
#pragma unroll
        for (int nt = 0; nt < 8; nt++) {
            int col = bn + nbase + nt * 8 + cpair;
            float bv0 = bias[col], bv1 = bias[col + 1];
            int m0 = bm + mbase + mt * 16 + r0;
            float2 v0 = make_float2(acc[mt][nt][0] + bv0, acc[mt][nt][1] + bv1);
            float2 v1 = make_float2(acc[mt][nt][2] + bv0, acc[mt][nt][3] + bv1);
            if (MODE == 0) {
                *(float2*)&Cout[(size_t)m0 * Nn + col] = v0;
                *(float2*)&Cout[(size_t)(m0 + 8) * Nn + col] = v1;
            } else {
                int s = col >> 10, rem = col & 1023;
                int h = rem >> 6, dd = rem & 63;
                float* dst = (s == 0) ? g_q : (s == 1) ? g_k : g_v;
                {
                    int b = m0 >> 12, n = m0 & 4095;
                    *(float2*)&dst[(((size_t)(b * HEADS + h) * SEQ + n) << 6) + dd] = v0;
                }
                {
                    int m1 = m0 + 8, b = m1 >> 12, n = m1 & 4095;
                    *(float2*)&dst[(((size_t)(b * HEADS + h) * SEQ + n) << 6) + dd] = v1;
                }
            }
        }
    }
}

// ---------------- conversions ----------------
__global__ void __launch_bounds__(256) convA(const float* __restrict__ X) {
    int i = blockIdx.x * 256 + threadIdx.x;
    int m = i >> 8;
    int k = (i & 255) << 2;
    float4 v = *(const float4*)(X + (size_t)m * CDIM + k);
    __nv_bfloat16 h0 = __float2bfloat16(v.x), h1 = __float2bfloat16(v.y);
    __nv_bfloat16 h2 = __float2bfloat16(v.z), h3 = __float2bfloat16(v.w);
    __nv_bfloat16 l0 = __float2bfloat16(v.x - __bfloat162float(h0));
    __nv_bfloat16 l1 = __float2bfloat16(v.y - __bfloat162float(h1));
    __nv_bfloat16 l2 = __float2bfloat16(v.z - __bfloat162float(h2));
    __nv_bfloat16 l3 = __float2bfloat16(v.w - __bfloat162float(h3));
    __nv_bfloat16* b = g_A + (size_t)m * K2 + k;
    __nv_bfloat162 H01; H01.x = h0; H01.y = h1;
    __nv_bfloat162 H23; H23.x = h2; H23.y = h3;
    __nv_bfloat162 L01; L01.x = l0; L01.y = l1;
    __nv_bfloat162 L23; L23.x = l2; L23.y = l3;
    ((__nv_bfloat162*)b)[0] = H01;           ((__nv_bfloat162*)b)[1] = H23;
    ((__nv_bfloat162*)(b + 1024))[0] = L01;  ((__nv_bfloat162*)(b + 1024))[1] = L23;
}

__global__ void __launch_bounds__(256) convWT(const float* __restrict__ W,
                                              __nv_bfloat16* __restrict__ out, int N) {
    __shared__ float t[32][33];
    int n0 = blockIdx.x * 32, k0 = blockIdx.y * 32;
    int tx = threadIdx.x & 31, ty = threadIdx.x >> 5;
#pragma unroll
    for (int i = 0; i < 4; i++)
        t[ty + i * 8][tx] = W[(size_t)(k0 + ty + i * 8) * N + n0 + tx];
    __syncthreads();
#pragma unroll
    for (int i = 0; i < 4; i++) {
        int nl = ty + i * 8;
        float v = t[tx][nl];
        __nv_bfloat16 hi = __float2bfloat16(v);
        __nv_bfloat16 lo = __float2bfloat16(v - __bfloat162float(hi));
        size_t row = (size_t)(n0 + nl) * K2;
        int k = k0 + tx;
        out[row + k] = hi;
        out[row + 1024 + k] = lo;
    }
}

// ---------------- middle: exp(k)^T v + colsum ----------------
__global__ void __launch_bounds__(256) ctx_partial() {
    const int bh = blockIdx.y, chunk = blockIdx.x;
    const float* kp = g_k + (size_t)bh * SEQ * HDIM;
    const float* vp = g_v + (size_t)bh * SEQ * HDIM;
    __shared__ float kt[32][65], vt[32][65], csred[256];
    const int tid = threadIdx.x, e = tid & 63, dg = tid >> 6;
    float acc[16];
#pragma unroll
    for (int j = 0; j < 16; j++) acc[j] = 0.f;
    float csum = 0.f;
    const int n0 = chunk * 256;
    for (int t = 0; t < 8; t++) {
        __syncthreads();
        for (int i = tid; i < 2048; i += 256) {
            int r = i >> 6, c = i & 63;
            size_t g = (size_t)(n0 + t * 32 + r) * 64 + c;
            float ex = __expf(kp[g]);
            kt[r][c] = ex;
            csum += ex;
            vt[r][c] = vp[g];
        }
        __syncthreads();
#pragma unroll 4
        for (int r = 0; r < 32; r++) {
            float vv = vt[r][e];
#pragma unroll
            for (int j = 0; j < 16; j++)
                acc[j] = fmaf(kt[r][dg * 16 + j], vv, acc[j]);
        }
    }
#pragma unroll
    for (int j = 0; j < 16; j++)
        atomicAdd(&g_ctx[((size_t)bh * 64 + dg * 16 + j) * 64 + e], acc[j]);
    csred[tid] = csum;
    __syncthreads();
    if (tid < 64)
        atomicAdd(&g_colsum[bh * 64 + tid],
                  csred[tid] + csred[tid + 64] + csred[tid + 128] + csred[tid + 192]);
}

// ---------------- softmax_D(q) @ ctx -> split-bf16 g_A ----------------
__global__ void __launch_bounds__(256) qattend() {
    const int bh = blockIdx.y;
    __shared__ float ctxs[64][65];
    __shared__ float rsum[64];
    __shared__ float pbuf[8][64];
    const int tid = threadIdx.x;
    if (tid < 64) rsum[tid] = 1.f / g_colsum[bh * 64 + tid];
    __syncthreads();
    for (int i = tid; i < 4096; i += 256) {
        int d = i >> 6, ee = i & 63;
        ctxs[d][ee] = g_ctx[((size_t)bh * 64 + d) * 64 + ee] * rsum[d];
    }
    __syncthreads();
    const int warp = tid >> 5, lane = tid & 31;
    const int b = bh >> 4, h = bh & 15;
    for (int rr = 0; rr < 4; rr++) {
        int n = blockIdx.x * 32 + warp * 4 + rr;
        const float* qrow = g_q + ((size_t)bh * SEQ + n) * 64;
        float q0 = qrow[lane], q1 = qrow[lane + 32];
        float mx = fmaxf(q0, q1);
#pragma unroll
        for (int o = 16; o; o >>= 1) mx = fmaxf(mx, __shfl_xor_sync(0xffffffffu, mx, o));
        float e0 = __expf(q0 - mx), e1 = __expf(q1 - mx);
        float s = e0 + e1;
#pragma unroll
        for (int o = 16; o; o >>= 1) s += __shfl_xor_sync(0xffffffffu, s, o);
        float inv = 1.f / s;
        pbuf[warp][lane] = e0 * inv;
        pbuf[warp][lane + 32] = e1 * inv;
        __syncwarp();
        float a0 = 0.f, a1 = 0.f;
#pragma unroll
        for (int d = 0; d < 64; d++) {
            float p = pbuf[warp][d];
            a0 = fmaf(p, ctxs[d][lane], a0);
            a1 = fmaf(p, ctxs[d][lane + 32], a1);
        }
        size_t m = (size_t)b * SEQ + n;
        int k0 = h * 64;
        __nv_bfloat16 h0 = __float2bfloat16(a0);
        __nv_bfloat16 l0 = __float2bfloat16(a0 - __bfloat162float(h0));
        __nv_bfloat16 h1 = __float2bfloat16(a1);
        __nv_bfloat16 l1 = __float2bfloat16(a1 - __bfloat162float(h1));
        __nv_bfloat16* base = g_A + m * K2;
        base[k0 + lane] = h0;         base[k0 + lane + 32] = h1;
        base[1024 + k0 + lane] = l0;  base[1024 + k0 + lane + 32] = l1;
        __syncwarp();
    }
}

// ---------------------------------------------------------------------------
extern "C" void kernel_launch(void* const* d_in, const int* in_sizes, int n_in,
                              void* d_out, int out_size) {
    const float* x      = (const float*)d_in[0];
    const float* W_qkv  = (const float*)d_in[1];
    const float* b_qkv  = (const float*)d_in[2];
    const float* W_proj = (const float*)d_in[3];
    const float* b_proj = (const float*)d_in[4];
    float* out = (float*)d_out;

    void *pa, *pbq, *pbp, *pctx, *pcs;
    cudaGetSymbolAddress(&pa,  g_A);
    cudaGetSymbolAddress(&pbq, g_Bq);
    cudaGetSymbolAddress(&pbp, g_Bp);
    cudaGetSymbolAddress(&pctx, g_ctx);
    cudaGetSymbolAddress(&pcs,  g_colsum);

    cudaFuncSetAttribute(gemm_hmma<0>, cudaFuncAttributeMaxDynamicSharedMemorySize, GSMEM);
    cudaFuncSetAttribute(gemm_hmma<1>, cudaFuncAttributeMaxDynamicSharedMemorySize, GSMEM);

    convA<<<MROWS * CDIM / 1024, 256>>>(x);
    convWT<<<dim3(3072 / 32, CDIM / 32), 256>>>(W_qkv, (__nv_bfloat16*)pbq, 3072);
    convWT<<<dim3(CDIM / 32, CDIM / 32), 256>>>(W_proj, (__nv_bfloat16*)pbp, CDIM);
    cudaMemsetAsync(pctx, 0, (size_t)BH * HDIM * HDIM * sizeof(float));
    cudaMemsetAsync(pcs,  0, (size_t)BH * HDIM * sizeof(float));

    gemm_hmma<1><<<dim3(3072 / 256, MROWS / 128), 256, GSMEM>>>(
        (const __nv_bfloat16*)pa, (const __nv_bfloat16*)pbq, b_qkv, nullptr, 3072);

    ctx_partial<<<dim3(SEQ / 256, BH), 256>>>();
    qattend<<<dim3(SEQ / 32, BH), 256>>>();

    gemm_hmma<0><<<dim3(CDIM / 256, MROWS / 128), 256, GSMEM>>>(
        (const __nv_bfloat16*)pa, (const __nv_bfloat16*)pbp, b_proj, out, CDIM);
}

// round 7
// speedup vs baseline: 1.6357x; 1.6357x over previous
#include <cuda_runtime.h>
#include <cuda_bf16.h>
#include <cstdint>
#include <math.h>

#define BATCH 4
#define SEQ   4096
#define CDIM  1024
#define HEADS 16
#define HDIM  64
#define MROWS 16384
#define BH    64
#define NIT   32            // K=1024, BK=32

// ---------------- scratch ----------------
__device__ float g_Af[(size_t)MROWS * CDIM];        // A permuted tf32 (frag-ready)
__device__ float g_Bq[(size_t)3072 * CDIM];         // W_qkv permuted tf32
__device__ float g_Bp[(size_t)CDIM * CDIM];         // W_proj permuted tf32
__device__ float g_attn[(size_t)MROWS * CDIM];      // attention out [m][1024]
__device__ float g_q[(size_t)MROWS * CDIM];
__device__ float g_k[(size_t)MROWS * CDIM];
__device__ float g_v[(size_t)MROWS * CDIM];
__device__ float g_ctx[BH * HDIM * HDIM];
__device__ float g_colsum[BH * HDIM];

__device__ __forceinline__ uint32_t smem_u32(const void* p) {
    uint32_t a;
    asm("{ .reg .u64 t; cvta.to.shared.u64 t, %1; cvt.u32.u64 %0, t; }" : "=r"(a) : "l"(p));
    return a;
}
__device__ __forceinline__ void cpa16(uint32_t saddr, const void* g) {
    asm volatile("cp.async.cg.shared.global [%0], [%1], 16;" :: "r"(saddr), "l"(g));
}
#define CPA_COMMIT() asm volatile("cp.async.commit_group;" ::: "memory")

__device__ __forceinline__ uint32_t tf32r(float f) {
    uint32_t u;
    asm("cvt.rna.tf32.f32 %0, %1;" : "=r"(u) : "f"(f));
    return u;
}
__device__ __forceinline__ void mma_tf32(float* d, const uint4 a, const uint2 b) {
    asm volatile("mma.sync.aligned.m16n8k8.row.col.f32.tf32.tf32.f32 "
        "{%0,%1,%2,%3}, {%4,%5,%6,%7}, {%8,%9}, {%0,%1,%2,%3};"
        : "+f"(d[0]), "+f"(d[1]), "+f"(d[2]), "+f"(d[3])
        : "r"(a.x), "r"(a.y), "r"(a.z), "r"(a.w), "r"(b.x), "r"(b.y));
}

// ---------------- TF32 GEMM ----------------
// C[M,Nn] = A[M,1024] x B[1024,Nn] + bias.
// A permuted: [mblk=m/16][kblk=k/8][lane][4]  (a0=(r,c) a1=(r+8,c) a2=(r,c+4) a3=(r+8,c+4); r=lane>>2,c=lane&3)
// B permuted: [nblk=n/8][kblk][lane][2]       (b0=(k=c,n=g) b1=(k=c+4,n=g); g=lane>>2)
// CTA 128x128, BK=32 (4 k8), 256 thr, warp tile 64x32, 3-stage cp.async.
#define ASTG  16384
#define STGB  32768
#define GSMEM (3 * STGB)    // 98304 -> 2 CTA/SM

__device__ __forceinline__ void load_stage(uint32_t dst,
        const float* __restrict__ A, const float* __restrict__ B,
        int it, int bmblk, int bnblk, int tid) {
    const int kb0 = it * 4;
#pragma unroll
    for (int l = 0; l < 4; l++) {               // A: 8 mblk x 2KB
        int c = tid + l * 256;
        int mb = c >> 7, rest = c & 127;
        cpa16(dst + (uint32_t)(mb * 2048 + rest * 16),
              A + ((size_t)(bmblk + mb) * 128 + kb0) * 128 + rest * 4);
    }
#pragma unroll
    for (int l = 0; l < 4; l++) {               // B: 16 nblk x 1KB
        int c = tid + l * 256;
        int nb = c >> 6, rest = c & 63;
        cpa16(dst + ASTG + (uint32_t)(nb * 1024 + rest * 16),
              B + ((size_t)(bnblk + nb) * 128 + kb0) * 64 + rest * 4);
    }
    CPA_COMMIT();
}

template<int MODE>
__global__ void __launch_bounds__(256)
gemm_tf32(const float* __restrict__ A, const float* __restrict__ Bm,
          const float* __restrict__ bias, float* __restrict__ Cout, int Nn)
{
    extern __shared__ char dsm[];
    const uint32_t s0 = smem_u32(dsm);

    const int tid = threadIdx.x, wid = tid >> 5, lane = tid & 31;
    const int bm = blockIdx.y * 128, bn = blockIdx.x * 128;
    const int bmblk = bm >> 4, bnblk = bn >> 3;
    const int mw = wid & 1, nw = wid >> 1;      // warp tile 64x32

    float acc[4][4][4];
#pragma unroll
    for (int i = 0; i < 4; i++)
#pragma unroll
        for (int j = 0; j < 4; j++)
#pragma unroll
            for (int r = 0; r < 4; r++) acc[i][j][r] = 0.f;

    load_stage(s0,        A, Bm, 0, bmblk, bnblk, tid);
    load_stage(s0 + STGB, A, Bm, 1, bmblk, bnblk, tid);

    for (int i = 0; i < NIT; i++) {
        if (i + 2 < NIT) asm volatile("cp.async.wait_group 1;" ::: "memory");
        else             asm volatile("cp.async.wait_group 0;" ::: "memory");
        __syncthreads();
        if (i + 2 < NIT)
            load_stage(s0 + ((i + 2) % 3) * STGB, A, Bm, i + 2, bmblk, bnblk, tid);

        const uint4* ap = (const uint4*)(dsm + (i % 3) * STGB);
        const uint2* bp = (const uint2*)(dsm + (i % 3) * STGB + ASTG);
#pragma unroll
        for (int kc = 0; kc < 4; kc++) {
            uint4 af[4];
            uint2 bf[4];
#pragma unroll
            for (int mt = 0; mt < 4; mt++)
                af[mt] = ap[((mw * 4 + mt) * 4 + kc) * 32 + lane];
#pragma unroll
            for (int nt = 0; nt < 4; nt++)
                bf[nt] = bp[((nw * 4 + nt) * 4 + kc) * 32 + lane];
#pragma unroll
            for (int mt = 0; mt < 4; mt++)
#pragma unroll
                for (int nt = 0; nt < 4; nt++)
                    mma_tf32(acc[mt][nt], af[mt], bf[nt]);
        }
    }

    // epilogue
    const int mbase = mw * 64, nbase = nw * 32;
    const int r0 = lane >> 2, cpair = (lane & 3) * 2;
#pragma unroll
    for (int mt = 0; mt < 4; mt++) {
#pragma unroll
        for (int nt = 0; nt < 4; nt++) {
            int col = bn + nbase + nt * 8 + cpair;
            float bv0 = bias[col], bv1 = bias[col + 1];
            int m0 = bm + mbase + mt * 16 + r0;
            float2 v0 = make_float2(acc[mt][nt][0] + bv0, acc[mt][nt][1] + bv1);
            float2 v1 = make_float2(acc[mt][nt][2] + bv0, acc[mt][nt][3] + bv1);
            if (MODE == 0) {
                *(float2*)&Cout[(size_t)m0 * Nn + col] = v0;
                *(float2*)&Cout[(size_t)(m0 + 8) * Nn + col] = v1;
            } else {
                int s = col >> 10, rem = col & 1023;
                int h = rem >> 6, dd = rem & 63;
                float* dst = (s == 0) ? g_q : (s == 1) ? g_k : g_v;
                {
                    int b = m0 >> 12, n = m0 & 4095;
                    *(float2*)&dst[(((size_t)(b * HEADS + h) * SEQ + n) << 6) + dd] = v0;
                }
                {
                    int m1 = m0 + 8, b = m1 >> 12, n = m1 & 4095;
                    *(float2*)&dst[(((size_t)(b * HEADS + h) * SEQ + n) << 6) + dd] = v1;
                }
            }
        }
    }
}

// ---------------- conversions ----------------
// src [Mr x 1024] fp32 row-major -> dst permuted tf32 (A layout). 8 warps/block, 1 tile/warp.
__global__ void __launch_bounds__(256) convA(const float* __restrict__ src,
                                             float* __restrict__ dst) {
    int w = blockIdx.x * 8 + (threadIdx.x >> 5);
    int lane = threadIdx.x & 31;
    int mb = w >> 7, kb = w & 127;
    int r = lane >> 2, c = lane & 3;
    const float* p = src + (size_t)(mb * 16) * CDIM + kb * 8;
    uint4 o;
    o.x = tf32r(p[(size_t)r * CDIM + c]);
    o.y = tf32r(p[(size_t)(r + 8) * CDIM + c]);
    o.z = tf32r(p[(size_t)r * CDIM + c + 4]);
    o.w = tf32r(p[(size_t)(r + 8) * CDIM + c + 4]);
    ((uint4*)dst)[((size_t)mb * 128 + kb) * 32 + lane] = o;
}

// W [1024 x N] fp32 -> dst permuted tf32 (B layout). 1 tile/warp; tiles = (N/8)*128.
__global__ void __launch_bounds__(256) convWT(const float* __restrict__ W,
                                              float* __restrict__ dst, int N) {
    int w = blockIdx.x * 8 + (threadIdx.x >> 5);
    int lane = threadIdx.x & 31;
    int nb = w >> 7, kb = w & 127;
    int g = lane >> 2, c = lane & 3;
    const float* p = W + (size_t)(kb * 8) * N + nb * 8 + g;
    uint2 o;
    o.x = tf32r(p[(size_t)c * N]);
    o.y = tf32r(p[(size_t)(c + 4) * N]);
    ((uint2*)dst)[((size_t)nb * 128 + kb) * 32 + lane] = o;
}

// ---------------- middle: exp(k)^T v + colsum ----------------
__global__ void __launch_bounds__(256) ctx_partial() {
    const int bh = blockIdx.y, chunk = blockIdx.x;
    const float* kp = g_k + (size_t)bh * SEQ * HDIM;
    const float* vp = g_v + (size_t)bh * SEQ * HDIM;
    __shared__ float kt[32][65], vt[32][65], csred[256];
    const int tid = threadIdx.x, e = tid & 63, dg = tid >> 6;
    float acc[16];
#pragma unroll
    for (int j = 0; j < 16; j++) acc[j] = 0.f;
    float csum = 0.f;
    const int n0 = chunk * 256;
    for (int t = 0; t < 8; t++) {
        __syncthreads();
        for (int i = tid; i < 2048; i += 256) {
            int r = i >> 6, c = i & 63;
            size_t g = (size_t)(n0 + t * 32 + r) * 64 + c;
            float ex = __expf(kp[g]);
            kt[r][c] = ex;
            csum += ex;
            vt[r][c] = vp[g];
        }
        __syncthreads();
#pragma unroll 4
        for (int r = 0; r < 32; r++) {
            float vv = vt[r][e];
#pragma unroll
            for (int j = 0; j < 16; j++)
                acc[j] = fmaf(kt[r][dg * 16 + j], vv, acc[j]);
        }
    }
#pragma unroll
    for (int j = 0; j < 16; j++)
        atomicAdd(&g_ctx[((size_t)bh * 64 + dg * 16 + j) * 64 + e], acc[j]);
    csred[tid] = csum;
    __syncthreads();
    if (tid < 64)
        atomicAdd(&g_colsum[bh * 64 + tid],
                  csred[tid] + csred[tid + 64] + csred[tid + 128] + csred[tid + 192]);
}

// ---------------- softmax_D(q) @ ctx -> g_attn [m][1024] fp32 ----------------
__global__ void __launch_bounds__(256) qattend() {
    const int bh = blockIdx.y;
    __shared__ float ctxs[64][65];
    __shared__ float rsum[64];
    __shared__ float pbuf[8][64];
    const int tid = threadIdx.x;
    if (tid < 64) rsum[tid] = 1.f / g_colsum[bh * 64 + tid];
    __syncthreads();
    for (int i = tid; i < 4096; i += 256) {
        int d = i >> 6, ee = i & 63;
        ctxs[d][ee] = g_ctx[((size_t)bh * 64 + d) * 64 + ee] * rsum[d];
    }
    __syncthreads();
    const int warp = tid >> 5, lane = tid & 31;
    const int b = bh >> 4, h = bh & 15;
    for (int rr = 0; rr < 4; rr++) {
        int n = blockIdx.x * 32 + warp * 4 + rr;
        const float* qrow = g_q + ((size_t)bh * SEQ + n) * 64;
        float q0 = qrow[lane], q1 = qrow[lane + 32];
        float mx = fmaxf(q0, q1);
#pragma unroll
        for (int o = 16; o; o >>= 1) mx = fmaxf(mx, __shfl_xor_sync(0xffffffffu, mx, o));
        float e0 = __expf(q0 - mx), e1 = __expf(q1 - mx);
        float s = e0 + e1;
#pragma unroll
        for (int o = 16; o; o >>= 1) s += __shfl_xor_sync(0xffffffffu, s, o);
        float inv = 1.f / s;
        pbuf[warp][lane] = e0 * inv;
        pbuf[warp][lane + 32] = e1 * inv;
        __syncwarp();
        float a0 = 0.f, a1 = 0.f;
#pragma unroll
        for (int d = 0; d < 64; d++) {
            float p = pbuf[warp][d];
            a0 = fmaf(p, ctxs[d][lane], a0);
            a1 = fmaf(p, ctxs[d][lane + 32], a1);
        }
        float* o = g_attn + ((size_t)b * SEQ + n) * CDIM + h * HDIM;
        o[lane] = a0;
        o[lane + 32] = a1;
        __syncwarp();
    }
}

// ---------------------------------------------------------------------------
extern "C" void kernel_launch(void* const* d_in, const int* in_sizes, int n_in,
                              void* d_out, int out_size) {
    const float* x      = (const float*)d_in[0];
    const float* W_qkv  = (const float*)d_in[1];
    const float* b_qkv  = (const float*)d_in[2];
    const float* W_proj = (const float*)d_in[3];
    const float* b_proj = (const float*)d_in[4];
    float* out = (float*)d_out;

    void *paf, *pbq, *pbp, *pattn, *pctx, *pcs;
    cudaGetSymbolAddress(&paf,  g_Af);
    cudaGetSymbolAddress(&pbq,  g_Bq);
    cudaGetSymbolAddress(&pbp,  g_Bp);
    cudaGetSymbolAddress(&pattn, g_attn);
    cudaGetSymbolAddress(&pctx, g_ctx);
    cudaGetSymbolAddress(&pcs,  g_colsum);

    cudaFuncSetAttribute(gemm_tf32<0>, cudaFuncAttributeMaxDynamicSharedMemorySize, GSMEM);
    cudaFuncSetAttribute(gemm_tf32<1>, cudaFuncAttributeMaxDynamicSharedMemorySize, GSMEM);

    // 1) permuted tf32 conversions
    convA<<<(MROWS / 16) * (CDIM / 8) / 8, 256>>>(x, (float*)paf);
    convWT<<<(3072 / 8) * 128 / 8, 256>>>(W_qkv, (float*)pbq, 3072);
    convWT<<<(CDIM / 8) * 128 / 8, 256>>>(W_proj, (float*)pbp, CDIM);
    cudaMemsetAsync(pctx, 0, (size_t)BH * HDIM * HDIM * sizeof(float));
    cudaMemsetAsync(pcs,  0, (size_t)BH * HDIM * sizeof(float));

    // 2) qkv GEMM (tf32), scatter to q/k/v
    gemm_tf32<1><<<dim3(3072 / 128, MROWS / 128), 256, GSMEM>>>(
        (const float*)paf, (const float*)pbq, b_qkv, nullptr, 3072);

    // 3) ctx = exp(k)^T v, colsum
    ctx_partial<<<dim3(SEQ / 256, BH), 256>>>();

    // 4) attn = softmax_D(q) @ (ctx/colsum) -> g_attn
    qattend<<<dim3(SEQ / 32, BH), 256>>>();

    // 5) re-permute attn for proj GEMM
    convA<<<(MROWS / 16) * (CDIM / 8) / 8, 256>>>((const float*)pattn, (float*)paf);

    // 6) proj GEMM (tf32)
    gemm_tf32<0><<<dim3(CDIM / 128, MROWS / 128), 256, GSMEM>>>(
        (const float*)paf, (const float*)pbp, b_proj, out, CDIM);
}

// round 8
// speedup vs baseline: 1.6737x; 1.0232x over previous
#include <cuda_runtime.h>
#include <cuda_bf16.h>
#include <cstdint>
#include <math.h>

#define BATCH 4
#define SEQ   4096
#define CDIM  1024
#define HEADS 16
#define HDIM  64
#define MROWS 16384
#define BH    64
#define NIT   32            // K=1024, BK=32

// ---------------- scratch ----------------
__device__ float g_Af[(size_t)MROWS * CDIM];        // A permuted tf32 (frag-ready)
__device__ float g_Bq[(size_t)3072 * CDIM];         // W_qkv permuted tf32
__device__ float g_Bp[(size_t)CDIM * CDIM];         // W_proj permuted tf32
__device__ float g_q[(size_t)MROWS * CDIM];
__device__ float g_k[(size_t)MROWS * CDIM];
__device__ float g_v[(size_t)MROWS * CDIM];
__device__ float g_ctx[BH * HDIM * HDIM];
__device__ float g_colsum[BH * HDIM];

__device__ __forceinline__ uint32_t smem_u32(const void* p) {
    uint32_t a;
    asm("{ .reg .u64 t; cvta.to.shared.u64 t, %1; cvt.u32.u64 %0, t; }" : "=r"(a) : "l"(p));
    return a;
}
__device__ __forceinline__ void cpa16(uint32_t saddr, const void* g) {
    asm volatile("cp.async.cg.shared.global [%0], [%1], 16;" :: "r"(saddr), "l"(g));
}
#define CPA_COMMIT() asm volatile("cp.async.commit_group;" ::: "memory")

__device__ __forceinline__ uint32_t tf32r(float f) {
    uint32_t u;
    asm("cvt.rna.tf32.f32 %0, %1;" : "=r"(u) : "f"(f));
    return u;
}
__device__ __forceinline__ void mma_tf32(float* d, const uint4 a, const uint2 b) {
    asm volatile("mma.sync.aligned.m16n8k8.row.col.f32.tf32.tf32.f32 "
        "{%0,%1,%2,%3}, {%4,%5,%6,%7}, {%8,%9}, {%0,%1,%2,%3};"
        : "+f"(d[0]), "+f"(d[1]), "+f"(d[2]), "+f"(d[3])
        : "r"(a.x), "r"(a.y), "r"(a.z), "r"(a.w), "r"(b.x), "r"(b.y));
}

// ---------------- TF32 GEMM ----------------
// A permuted: [mblk=m/16][kblk=k/8][lane][4], B permuted: [nblk=n/8][kblk][lane][2]
// CTA 128x128, BK=32 (4 k8), 256 thr, warp tile 64x32, 3-stage cp.async.
#define ASTG  16384
#define STGB  32768
#define GSMEM (3 * STGB)    // 98304 -> 2 CTA/SM

__device__ __forceinline__ void load_stage(uint32_t dst,
        const float* __restrict__ A, const float* __restrict__ B,
        int it, int bmblk, int bnblk, int tid) {
    const int kb0 = it * 4;
#pragma unroll
    for (int l = 0; l < 4; l++) {               // A: 8 mblk x 2KB
        int c = tid + l * 256;
        int mb = c >> 7, rest = c & 127;
        cpa16(dst + (uint32_t)(mb * 2048 + rest * 16),
              A + ((size_t)(bmblk + mb) * 128 + kb0) * 128 + rest * 4);
    }
#pragma unroll
    for (int l = 0; l < 4; l++) {               // B: 16 nblk x 1KB
        int c = tid + l * 256;
        int nb = c >> 6, rest = c & 63;
        cpa16(dst + ASTG + (uint32_t)(nb * 1024 + rest * 16),
              B + ((size_t)(bnblk + nb) * 128 + kb0) * 64 + rest * 4);
    }
    CPA_COMMIT();
}

template<int MODE>
__global__ void __launch_bounds__(256)
gemm_tf32(const float* __restrict__ A, const float* __restrict__ Bm,
          const float* __restrict__ bias, float* __restrict__ Cout, int Nn)
{
    extern __shared__ char dsm[];
    const uint32_t s0 = smem_u32(dsm);

    const int tid = threadIdx.x, wid = tid >> 5, lane = tid & 31;
    const int bm = blockIdx.y * 128, bn = blockIdx.x * 128;
    const int bmblk = bm >> 4, bnblk = bn >> 3;
    const int mw = wid & 1, nw = wid >> 1;      // warp tile 64x32

    float acc[4][4][4];
#pragma unroll
    for (int i = 0; i < 4; i++)
#pragma unroll
        for (int j = 0; j < 4; j++)
#pragma unroll
            for (int r = 0; r < 4; r++) acc[i][j][r] = 0.f;

    load_stage(s0,        A, Bm, 0, bmblk, bnblk, tid);
    load_stage(s0 + STGB, A, Bm, 1, bmblk, bnblk, tid);

    for (int i = 0; i < NIT; i++) {
        if (i + 2 < NIT) asm volatile("cp.async.wait_group 1;" ::: "memory");
        else             asm volatile("cp.async.wait_group 0;" ::: "memory");
        __syncthreads();
        if (i + 2 < NIT)
            load_stage(s0 + ((i + 2) % 3) * STGB, A, Bm, i + 2, bmblk, bnblk, tid);

        // per-warp lane-hoisted fragment pointers (immediate LDS offsets)
        const uint4* apw = (const uint4*)(dsm + (i % 3) * STGB) + mw * 16 * 32 + lane;
        const uint2* bpw = (const uint2*)(dsm + (i % 3) * STGB + ASTG) + nw * 16 * 32 + lane;
#pragma unroll
        for (int kc = 0; kc < 4; kc++) {
            uint4 af[4];
            uint2 bf[4];
#pragma unroll
            for (int mt = 0; mt < 4; mt++)
                af[mt] = apw[(mt * 4 + kc) * 32];
#pragma unroll
            for (int nt = 0; nt < 4; nt++)
                bf[nt] = bpw[(nt * 4 + kc) * 32];
#pragma unroll
            for (int mt = 0; mt < 4; mt++)
#pragma unroll
                for (int nt = 0; nt < 4; nt++)
                    mma_tf32(acc[mt][nt], af[mt], bf[nt]);
        }
    }

    // epilogue
    const int mbase = mw * 64, nbase = nw * 32;
    const int r0 = lane >> 2, cpair = (lane & 3) * 2;
#pragma unroll
    for (int mt = 0; mt < 4; mt++) {
#pragma unroll
        for (int nt = 0; nt < 4; nt++) {
            int col = bn + nbase + nt * 8 + cpair;
            float bv0 = bias[col], bv1 = bias[col + 1];
            int m0 = bm + mbase + mt * 16 + r0;
            float2 v0 = make_float2(acc[mt][nt][0] + bv0, acc[mt][nt][1] + bv1);
            float2 v1 = make_float2(acc[mt][nt][2] + bv0, acc[mt][nt][3] + bv1);
            if (MODE == 0) {
                *(float2*)&Cout[(size_t)m0 * Nn + col] = v0;
                *(float2*)&Cout[(size_t)(m0 + 8) * Nn + col] = v1;
            } else {
                int s = col >> 10, rem = col & 1023;
                int h = rem >> 6, dd = rem & 63;
                float* dst = (s == 0) ? g_q : (s == 1) ? g_k : g_v;
                {
                    int b = m0 >> 12, n = m0 & 4095;
                    *(float2*)&dst[(((size_t)(b * HEADS + h) * SEQ + n) << 6) + dd] = v0;
                }
                {
                    int m1 = m0 + 8, b = m1 >> 12, n = m1 & 4095;
                    *(float2*)&dst[(((size_t)(b * HEADS + h) * SEQ + n) << 6) + dd] = v1;
                }
            }
        }
    }
}

// ---------------- conversions ----------------
__global__ void __launch_bounds__(256) convA(const float* __restrict__ src,
                                             float* __restrict__ dst) {
    int w = blockIdx.x * 8 + (threadIdx.x >> 5);
    int lane = threadIdx.x & 31;
    int mb = w >> 7, kb = w & 127;
    int r = lane >> 2, c = lane & 3;
    const float* p = src + (size_t)(mb * 16) * CDIM + kb * 8;
    uint4 o;
    o.x = tf32r(p[(size_t)r * CDIM + c]);
    o.y = tf32r(p[(size_t)(r + 8) * CDIM + c]);
    o.z = tf32r(p[(size_t)r * CDIM + c + 4]);
    o.w = tf32r(p[(size_t)(r + 8) * CDIM + c + 4]);
    ((uint4*)dst)[((size_t)mb * 128 + kb) * 32 + lane] = o;
}

__global__ void __launch_bounds__(256) convWT(const float* __restrict__ W,
                                              float* __restrict__ dst, int N) {
    int w = blockIdx.x * 8 + (threadIdx.x >> 5);
    int lane = threadIdx.x & 31;
    int nb = w >> 7, kb = w & 127;
    int g = lane >> 2, c = lane & 3;
    const float* p = W + (size_t)(kb * 8) * N + nb * 8 + g;
    uint2 o;
    o.x = tf32r(p[(size_t)c * N]);
    o.y = tf32r(p[(size_t)(c + 4) * N]);
    ((uint2*)dst)[((size_t)nb * 128 + kb) * 32 + lane] = o;
}

// ---------------- middle: exp(k)^T v + colsum ----------------
__global__ void __launch_bounds__(256) ctx_partial() {
    const int bh = blockIdx.y, chunk = blockIdx.x;
    const float* kp = g_k + (size_t)bh * SEQ * HDIM;
    const float* vp = g_v + (size_t)bh * SEQ * HDIM;
    __shared__ float kt[32][65], vt[32][65], csred[256];
    const int tid = threadIdx.x, e = tid & 63, dg = tid >> 6;
    float acc[16];
#pragma unroll
    for (int j = 0; j < 16; j++) acc[j] = 0.f;
    float csum = 0.f;
    const int n0 = chunk * 256;
    for (int t = 0; t < 8; t++) {
        __syncthreads();
        for (int i = tid; i < 2048; i += 256) {
            int r = i >> 6, c = i & 63;
            size_t g = (size_t)(n0 + t * 32 + r) * 64 + c;
            float ex = __expf(kp[g]);
            kt[r][c] = ex;
            csum += ex;
            vt[r][c] = vp[g];
        }
        __syncthreads();
#pragma unroll 4
        for (int r = 0; r < 32; r++) {
            float vv = vt[r][e];
#pragma unroll
            for (int j = 0; j < 16; j++)
                acc[j] = fmaf(kt[r][dg * 16 + j], vv, acc[j]);
        }
    }
#pragma unroll
    for (int j = 0; j < 16; j++)
        atomicAdd(&g_ctx[((size_t)bh * 64 + dg * 16 + j) * 64 + e], acc[j]);
    csred[tid] = csum;
    __syncthreads();
    if (tid < 64)
        atomicAdd(&g_colsum[bh * 64 + tid],
                  csred[tid] + csred[tid + 64] + csred[tid + 128] + csred[tid + 192]);
}

// ---------------- softmax_D(q) @ ctx -> permuted tf32 g_Af (fused) ----------------
__global__ void __launch_bounds__(256) qattend() {
    const int bh = blockIdx.y;
    __shared__ float ctxs[64][65];
    __shared__ float rsum[64];
    __shared__ float pbuf[8][64];
    __shared__ float sout[32][68];
    const int tid = threadIdx.x;
    if (tid < 64) rsum[tid] = 1.f / g_colsum[bh * 64 + tid];
    __syncthreads();
    for (int i = tid; i < 4096; i += 256) {
        int d = i >> 6, ee = i & 63;
        ctxs[d][ee] = g_ctx[((size_t)bh * 64 + d) * 64 + ee] * rsum[d];
    }
    __syncthreads();
    const int warp = tid >> 5, lane = tid & 31;
    const int b = bh >> 4, h = bh & 15;
    for (int rr = 0; rr < 4; rr++) {
        int lr = warp * 4 + rr;                  // local row 0..31
        int n = blockIdx.x * 32 + lr;
        const float* qrow = g_q + ((size_t)bh * SEQ + n) * 64;
        float q0 = qrow[lane], q1 = qrow[lane + 32];
        float mx = fmaxf(q0, q1);
#pragma unroll
        for (int o = 16; o; o >>= 1) mx = fmaxf(mx, __shfl_xor_sync(0xffffffffu, mx, o));
        float e0 = __expf(q0 - mx), e1 = __expf(q1 - mx);
        float s = e0 + e1;
#pragma unroll
        for (int o = 16; o; o >>= 1) s += __shfl_xor_sync(0xffffffffu, s, o);
        float inv = 1.f / s;
        pbuf[warp][lane] = e0 * inv;
        pbuf[warp][lane + 32] = e1 * inv;
        __syncwarp();
        float a0 = 0.f, a1 = 0.f;
#pragma unroll
        for (int d = 0; d < 64; d++) {
            float p = pbuf[warp][d];
            a0 = fmaf(p, ctxs[d][lane], a0);
            a1 = fmaf(p, ctxs[d][lane + 32], a1);
        }
        sout[lr][lane] = a0;
        sout[lr][lane + 32] = a1;
        __syncwarp();
    }
    __syncthreads();

    // permuted tf32 write: 16 tiles (2 mblk x 8 kblk), 2 per warp
    const int mblk0 = (b * SEQ + blockIdx.x * 32) >> 4;
    const int r = lane >> 2, c = lane & 3;
#pragma unroll
    for (int t = 0; t < 2; t++) {
        int idx = warp * 2 + t;
        int mb = idx >> 3, kb = idx & 7;
        uint4 o;
        o.x = tf32r(sout[mb * 16 + r][kb * 8 + c]);
        o.y = tf32r(sout[mb * 16 + r + 8][kb * 8 + c]);
        o.z = tf32r(sout[mb * 16 + r][kb * 8 + c + 4]);
        o.w = tf32r(sout[mb * 16 + r + 8][kb * 8 + c + 4]);
        ((uint4*)g_Af)[((size_t)(mblk0 + mb) * 128 + (h * 8 + kb)) * 32 + lane] = o;
    }
}

// ---------------------------------------------------------------------------
extern "C" void kernel_launch(void* const* d_in, const int* in_sizes, int n_in,
                              void* d_out, int out_size) {
    const float* x      = (const float*)d_in[0];
    const float* W_qkv  = (const float*)d_in[1];
    const float* b_qkv  = (const float*)d_in[2];
    const float* W_proj = (const float*)d_in[3];
    const float* b_proj = (const float*)d_in[4];
    float* out = (float*)d_out;

    void *paf, *pbq, *pbp, *pctx, *pcs;
    cudaGetSymbolAddress(&paf,  g_Af);
    cudaGetSymbolAddress(&pbq,  g_Bq);
    cudaGetSymbolAddress(&pbp,  g_Bp);
    cudaGetSymbolAddress(&pctx, g_ctx);
    cudaGetSymbolAddress(&pcs,  g_colsum);

    cudaFuncSetAttribute(gemm_tf32<0>, cudaFuncAttributeMaxDynamicSharedMemorySize, GSMEM);
    cudaFuncSetAttribute(gemm_tf32<1>, cudaFuncAttributeMaxDynamicSharedMemorySize, GSMEM);

    // 1) permuted tf32 conversions
    convA<<<(MROWS / 16) * (CDIM / 8) / 8, 256>>>(x, (float*)paf);
    convWT<<<(3072 / 8) * 128 / 8, 256>>>(W_qkv, (float*)pbq, 3072);
    convWT<<<(CDIM / 8) * 128 / 8, 256>>>(W_proj, (float*)pbp, CDIM);
    cudaMemsetAsync(pctx, 0, (size_t)BH * HDIM * HDIM * sizeof(float));
    cudaMemsetAsync(pcs,  0, (size_t)BH * HDIM * sizeof(float));

    // 2) qkv GEMM (tf32), scatter to q/k/v
    gemm_tf32<1><<<dim3(3072 / 128, MROWS / 128), 256, GSMEM>>>(
        (const float*)paf, (const float*)pbq, b_qkv, nullptr, 3072);

    // 3) ctx = exp(k)^T v, colsum
    ctx_partial<<<dim3(SEQ / 256, BH), 256>>>();

    // 4) attn = softmax_D(q) @ (ctx/colsum) -> permuted tf32 g_Af (fused)
    qattend<<<dim3(SEQ / 32, BH), 256>>>();

    // 5) proj GEMM (tf32)
    gemm_tf32<0><<<dim3(CDIM / 128, MROWS / 128), 256, GSMEM>>>(
        (const float*)paf, (const float*)pbp, b_proj, out, CDIM);
}

// round 9
// speedup vs baseline: 1.8245x; 1.0901x over previous
#include <cuda_runtime.h>
#include <cuda_bf16.h>
#include <cstdint>
#include <math.h>

#define BATCH 4
#define SEQ   4096
#define CDIM  1024
#define HEADS 16
#define HDIM  64
#define MROWS 16384
#define BH    64
#define NIT   32            // K=1024, BK=32

// ---------------- scratch ----------------
__device__ float g_Af[(size_t)MROWS * CDIM];        // A permuted tf32 (frag-ready)
__device__ float g_Bq[(size_t)3072 * CDIM];         // W_qkv permuted tf32
__device__ float g_Bp[(size_t)CDIM * CDIM];         // W_proj permuted tf32
__device__ float g_q[(size_t)MROWS * CDIM];
__device__ float g_k[(size_t)MROWS * CDIM];
__device__ float g_v[(size_t)MROWS * CDIM];
__device__ float g_ctx[BH * HDIM * HDIM];
__device__ float g_colsum[BH * HDIM];

__device__ __forceinline__ uint32_t smem_u32(const void* p) {
    uint32_t a;
    asm("{ .reg .u64 t; cvta.to.shared.u64 t, %1; cvt.u32.u64 %0, t; }" : "=r"(a) : "l"(p));
    return a;
}
__device__ __forceinline__ void cpa16(uint32_t saddr, const void* g) {
    asm volatile("cp.async.cg.shared.global [%0], [%1], 16;" :: "r"(saddr), "l"(g));
}
#define CPA_COMMIT() asm volatile("cp.async.commit_group;" ::: "memory")

__device__ __forceinline__ uint32_t tf32r(float f) {
    uint32_t u;
    asm("cvt.rna.tf32.f32 %0, %1;" : "=r"(u) : "f"(f));
    return u;
}
__device__ __forceinline__ void mma_tf32(float* d, const uint4 a, const uint2 b) {
    asm volatile("mma.sync.aligned.m16n8k8.row.col.f32.tf32.tf32.f32 "
        "{%0,%1,%2,%3}, {%4,%5,%6,%7}, {%8,%9}, {%0,%1,%2,%3};"
        : "+f"(d[0]), "+f"(d[1]), "+f"(d[2]), "+f"(d[3])
        : "r"(a.x), "r"(a.y), "r"(a.z), "r"(a.w), "r"(b.x), "r"(b.y));
}

// ---------------- TF32 GEMM (unchanged from R8) ----------------
#define ASTG  16384
#define STGB  32768
#define GSMEM (3 * STGB)    // 98304 -> 2 CTA/SM

__device__ __forceinline__ void load_stage(uint32_t dst,
        const float* __restrict__ A, const float* __restrict__ B,
        int it, int bmblk, int bnblk, int tid) {
    const int kb0 = it * 4;
#pragma unroll
    for (int l = 0; l < 4; l++) {               // A: 8 mblk x 2KB
        int c = tid + l * 256;
        int mb = c >> 7, rest = c & 127;
        cpa16(dst + (uint32_t)(mb * 2048 + rest * 16),
              A + ((size_t)(bmblk + mb) * 128 + kb0) * 128 + rest * 4);
    }
#pragma unroll
    for (int l = 0; l < 4; l++) {               // B: 16 nblk x 1KB
        int c = tid + l * 256;
        int nb = c >> 6, rest = c & 63;
        cpa16(dst + ASTG + (uint32_t)(nb * 1024 + rest * 16),
              B + ((size_t)(bnblk + nb) * 128 + kb0) * 64 + rest * 4);
    }
    CPA_COMMIT();
}

template<int MODE>
__global__ void __launch_bounds__(256)
gemm_tf32(const float* __restrict__ A, const float* __restrict__ Bm,
          const float* __restrict__ bias, float* __restrict__ Cout, int Nn)
{
    extern __shared__ char dsm[];
    const uint32_t s0 = smem_u32(dsm);

    const int tid = threadIdx.x, wid = tid >> 5, lane = tid & 31;
    const int bm = blockIdx.y * 128, bn = blockIdx.x * 128;
    const int bmblk = bm >> 4, bnblk = bn >> 3;
    const int mw = wid & 1, nw = wid >> 1;

    float acc[4][4][4];
#pragma unroll
    for (int i = 0; i < 4; i++)
#pragma unroll
        for (int j = 0; j < 4; j++)
#pragma unroll
            for (int r = 0; r < 4; r++) acc[i][j][r] = 0.f;

    load_stage(s0,        A, Bm, 0, bmblk, bnblk, tid);
    load_stage(s0 + STGB, A, Bm, 1, bmblk, bnblk, tid);

    for (int i = 0; i < NIT; i++) {
        if (i + 2 < NIT) asm volatile("cp.async.wait_group 1;" ::: "memory");
        else             asm volatile("cp.async.wait_group 0;" ::: "memory");
        __syncthreads();
        if (i + 2 < NIT)
            load_stage(s0 + ((i + 2) % 3) * STGB, A, Bm, i + 2, bmblk, bnblk, tid);

        const uint4* apw = (const uint4*)(dsm + (i % 3) * STGB) + mw * 16 * 32 + lane;
        const uint2* bpw = (const uint2*)(dsm + (i % 3) * STGB + ASTG) + nw * 16 * 32 + lane;
#pragma unroll
        for (int kc = 0; kc < 4; kc++) {
            uint4 af[4];
            uint2 bf[4];
#pragma unroll
            for (int mt = 0; mt < 4; mt++)
                af[mt] = apw[(mt * 4 + kc) * 32];
#pragma unroll
            for (int nt = 0; nt < 4; nt++)
                bf[nt] = bpw[(nt * 4 + kc) * 32];
#pragma unroll
            for (int mt = 0; mt < 4; mt++)
#pragma unroll
                for (int nt = 0; nt < 4; nt++)
                    mma_tf32(acc[mt][nt], af[mt], bf[nt]);
        }
    }

    const int mbase = mw * 64, nbase = nw * 32;
    const int r0 = lane >> 2, cpair = (lane & 3) * 2;
#pragma unroll
    for (int mt = 0; mt < 4; mt++) {
#pragma unroll
        for (int nt = 0; nt < 4; nt++) {
            int col = bn + nbase + nt * 8 + cpair;
            float bv0 = bias[col], bv1 = bias[col + 1];
            int m0 = bm + mbase + mt * 16 + r0;
            float2 v0 = make_float2(acc[mt][nt][0] + bv0, acc[mt][nt][1] + bv1);
            float2 v1 = make_float2(acc[mt][nt][2] + bv0, acc[mt][nt][3] + bv1);
            if (MODE == 0) {
                *(float2*)&Cout[(size_t)m0 * Nn + col] = v0;
                *(float2*)&Cout[(size_t)(m0 + 8) * Nn + col] = v1;
            } else {
                int s = col >> 10, rem = col & 1023;
                int h = rem >> 6, dd = rem & 63;
                float* dst = (s == 0) ? g_q : (s == 1) ? g_k : g_v;
                {
                    int b = m0 >> 12, n = m0 & 4095;
                    *(float2*)&dst[(((size_t)(b * HEADS + h) * SEQ + n) << 6) + dd] = v0;
                }
                {
                    int m1 = m0 + 8, b = m1 >> 12, n = m1 & 4095;
                    *(float2*)&dst[(((size_t)(b * HEADS + h) * SEQ + n) << 6) + dd] = v1;
                }
            }
        }
    }
}

// ---------------- conversions ----------------
__global__ void __launch_bounds__(256) convA(const float* __restrict__ src,
                                             float* __restrict__ dst) {
    int w = blockIdx.x * 8 + (threadIdx.x >> 5);
    int lane = threadIdx.x & 31;
    int mb = w >> 7, kb = w & 127;
    int r = lane >> 2, c = lane & 3;
    const float* p = src + (size_t)(mb * 16) * CDIM + kb * 8;
    uint4 o;
    o.x = tf32r(p[(size_t)r * CDIM + c]);
    o.y = tf32r(p[(size_t)(r + 8) * CDIM + c]);
    o.z = tf32r(p[(size_t)r * CDIM + c + 4]);
    o.w = tf32r(p[(size_t)(r + 8) * CDIM + c + 4]);
    ((uint4*)dst)[((size_t)mb * 128 + kb) * 32 + lane] = o;
}

__global__ void __launch_bounds__(256) convWT(const float* __restrict__ W,
                                              float* __restrict__ dst, int N) {
    int w = blockIdx.x * 8 + (threadIdx.x >> 5);
    int lane = threadIdx.x & 31;
    int nb = w >> 7, kb = w & 127;
    int g = lane >> 2, c = lane & 3;
    const float* p = W + (size_t)(kb * 8) * N + nb * 8 + g;
    uint2 o;
    o.x = tf32r(p[(size_t)c * N]);
    o.y = tf32r(p[(size_t)(c + 4) * N]);
    ((uint2*)dst)[((size_t)nb * 128 + kb) * 32 + lane] = o;
}

// ---------------- middle: exp(k)^T v + colsum (vectorized LDS) ----------------
__global__ void __launch_bounds__(256) ctx_partial() {
    const int bh = blockIdx.y, chunk = blockIdx.x;
    const float* kp = g_k + (size_t)bh * SEQ * HDIM;
    const float* vp = g_v + (size_t)bh * SEQ * HDIM;
    __shared__ float kt[32][72], vt[32][72];
    __shared__ float csred[256];
    const int tid = threadIdx.x, e = tid & 63, dg = tid >> 6;
    float acc[16];
#pragma unroll
    for (int j = 0; j < 16; j++) acc[j] = 0.f;
    float csum = 0.f;
    const int n0 = chunk * 256;
    for (int t = 0; t < 8; t++) {
        __syncthreads();
        for (int i = tid; i < 2048; i += 256) {
            int r = i >> 6, c = i & 63;
            size_t g = (size_t)(n0 + t * 32 + r) * 64 + c;
            float ex = __expf(kp[g]);
            kt[r][c] = ex;
            csum += ex;
            vt[r][c] = vp[g];
        }
        __syncthreads();
#pragma unroll 2
        for (int r = 0; r < 32; r++) {
            float vv = vt[r][e];
            const float4* k4 = (const float4*)&kt[r][dg * 16];
            float4 ka = k4[0], kb = k4[1], kc = k4[2], kd = k4[3];
            acc[0]  = fmaf(ka.x, vv, acc[0]);
            acc[1]  = fmaf(ka.y, vv, acc[1]);
            acc[2]  = fmaf(ka.z, vv, acc[2]);
            acc[3]  = fmaf(ka.w, vv, acc[3]);
            acc[4]  = fmaf(kb.x, vv, acc[4]);
            acc[5]  = fmaf(kb.y, vv, acc[5]);
            acc[6]  = fmaf(kb.z, vv, acc[6]);
            acc[7]  = fmaf(kb.w, vv, acc[7]);
            acc[8]  = fmaf(kc.x, vv, acc[8]);
            acc[9]  = fmaf(kc.y, vv, acc[9]);
            acc[10] = fmaf(kc.z, vv, acc[10]);
            acc[11] = fmaf(kc.w, vv, acc[11]);
            acc[12] = fmaf(kd.x, vv, acc[12]);
            acc[13] = fmaf(kd.y, vv, acc[13]);
            acc[14] = fmaf(kd.z, vv, acc[14]);
            acc[15] = fmaf(kd.w, vv, acc[15]);
        }
    }
#pragma unroll
    for (int j = 0; j < 16; j++)
        atomicAdd(&g_ctx[((size_t)bh * 64 + dg * 16 + j) * 64 + e], acc[j]);
    csred[tid] = csum;
    __syncthreads();
    if (tid < 64)
        atomicAdd(&g_colsum[bh * 64 + tid],
                  csred[tid] + csred[tid + 64] + csred[tid + 128] + csred[tid + 192]);
}

// ---------------- softmax_D(q) @ ctx -> permuted tf32 g_Af (fused, 4-row batched) ----------------
__global__ void __launch_bounds__(256) qattend() {
    const int bh = blockIdx.y;
    __shared__ float ctxs[64][65];
    __shared__ float rsum[64];
    __shared__ float pb[8][4][64];
    __shared__ float sout[32][68];
    const int tid = threadIdx.x;
    if (tid < 64) rsum[tid] = 1.f / g_colsum[bh * 64 + tid];
    __syncthreads();
    for (int i = tid; i < 4096; i += 256) {
        int d = i >> 6, ee = i & 63;
        ctxs[d][ee] = g_ctx[((size_t)bh * 64 + d) * 64 + ee] * rsum[d];
    }
    __syncthreads();
    const int warp = tid >> 5, lane = tid & 31;
    const int b = bh >> 4, h = bh & 15;

    // phase 1: softmax for the warp's 4 rows
#pragma unroll
    for (int rr = 0; rr < 4; rr++) {
        int n = blockIdx.x * 32 + warp * 4 + rr;
        const float* qrow = g_q + ((size_t)bh * SEQ + n) * 64;
        float q0 = qrow[lane], q1 = qrow[lane + 32];
        float mx = fmaxf(q0, q1);
#pragma unroll
        for (int o = 16; o; o >>= 1) mx = fmaxf(mx, __shfl_xor_sync(0xffffffffu, mx, o));
        float e0 = __expf(q0 - mx), e1 = __expf(q1 - mx);
        float s = e0 + e1;
#pragma unroll
        for (int o = 16; o; o >>= 1) s += __shfl_xor_sync(0xffffffffu, s, o);
        float inv = 1.f / s;
        pb[warp][rr][lane] = e0 * inv;
        pb[warp][rr][lane + 32] = e1 * inv;
    }
    __syncwarp();

    // phase 2: 4 rows share each ctxs load
    float a0[4] = {0.f, 0.f, 0.f, 0.f}, a1[4] = {0.f, 0.f, 0.f, 0.f};
#pragma unroll
    for (int d = 0; d < 64; d++) {
        float c0 = ctxs[d][lane], c1 = ctxs[d][lane + 32];
#pragma unroll
        for (int rr = 0; rr < 4; rr++) {
            float p = pb[warp][rr][d];
            a0[rr] = fmaf(p, c0, a0[rr]);
            a1[rr] = fmaf(p, c1, a1[rr]);
        }
    }
#pragma unroll
    for (int rr = 0; rr < 4; rr++) {
        int lr = warp * 4 + rr;
        sout[lr][lane] = a0[rr];
        sout[lr][lane + 32] = a1[rr];
    }
    __syncthreads();

    // permuted tf32 write: 16 tiles (2 mblk x 8 kblk), 2 per warp
    const int mblk0 = (b * SEQ + blockIdx.x * 32) >> 4;
    const int r = lane >> 2, c = lane & 3;
#pragma unroll
    for (int t = 0; t < 2; t++) {
        int idx = warp * 2 + t;
        int mb = idx >> 3, kb = idx & 7;
        uint4 o;
        o.x = tf32r(sout[mb * 16 + r][kb * 8 + c]);
        o.y = tf32r(sout[mb * 16 + r + 8][kb * 8 + c]);
        o.z = tf32r(sout[mb * 16 + r][kb * 8 + c + 4]);
        o.w = tf32r(sout[mb * 16 + r + 8][kb * 8 + c + 4]);
        ((uint4*)g_Af)[((size_t)(mblk0 + mb) * 128 + (h * 8 + kb)) * 32 + lane] = o;
    }
}

// ---------------------------------------------------------------------------
extern "C" void kernel_launch(void* const* d_in, const int* in_sizes, int n_in,
                              void* d_out, int out_size) {
    const float* x      = (const float*)d_in[0];
    const float* W_qkv  = (const float*)d_in[1];
    const float* b_qkv  = (const float*)d_in[2];
    const float* W_proj = (const float*)d_in[3];
    const float* b_proj = (const float*)d_in[4];
    float* out = (float*)d_out;

    void *paf, *pbq, *pbp, *pctx, *pcs;
    cudaGetSymbolAddress(&paf,  g_Af);
    cudaGetSymbolAddress(&pbq,  g_Bq);
    cudaGetSymbolAddress(&pbp,  g_Bp);
    cudaGetSymbolAddress(&pctx, g_ctx);
    cudaGetSymbolAddress(&pcs,  g_colsum);

    cudaFuncSetAttribute(gemm_tf32<0>, cudaFuncAttributeMaxDynamicSharedMemorySize, GSMEM);
    cudaFuncSetAttribute(gemm_tf32<1>, cudaFuncAttributeMaxDynamicSharedMemorySize, GSMEM);

    convA<<<(MROWS / 16) * (CDIM / 8) / 8, 256>>>(x, (float*)paf);
    convWT<<<(3072 / 8) * 128 / 8, 256>>>(W_qkv, (float*)pbq, 3072);
    convWT<<<(CDIM / 8) * 128 / 8, 256>>>(W_proj, (float*)pbp, CDIM);
    cudaMemsetAsync(pctx, 0, (size_t)BH * HDIM * HDIM * sizeof(float));
    cudaMemsetAsync(pcs,  0, (size_t)BH * HDIM * sizeof(float));

    gemm_tf32<1><<<dim3(3072 / 128, MROWS / 128), 256, GSMEM>>>(
        (const float*)paf, (const float*)pbq, b_qkv, nullptr, 3072);

    ctx_partial<<<dim3(SEQ / 256, BH), 256>>>();
    qattend<<<dim3(SEQ / 32, BH), 256>>>();

    gemm_tf32<0><<<dim3(CDIM / 128, MROWS / 128), 256, GSMEM>>>(
        (const float*)paf, (const float*)pbp, b_proj, out, CDIM);
}